// round 10
// baseline (speedup 1.0000x reference)
#include <cuda_runtime.h>
#include <cuda_bf16.h>
#include <math.h>
#include <stdint.h>

#define TT 64
#define DIMM 2048
#define SLOTSS 256
#define KS 8
#define KPER (DIMM / KS)     // 256
#define NCHUNK (KPER / 16)   // 16
#define NBLK 32              // n-tiles per big GEMM
#define SPAD 40
#define NB 256

// -------- device scratch --------
// layer outputs as packed bf16 planes: [0 .. TT*DIMM) = hi, [TT*DIMM ..) = lo
__device__ __nv_bfloat16 g_hbf[2 * TT * DIMM];
__device__ __nv_bfloat16 g_xbf[2 * TT * DIMM];
__device__ __nv_bfloat16 g_lvbf[2 * TT * DIMM];
__device__ __nv_bfloat16 g_gatedbf[2 * TT * DIMM];
__device__ float g_x[TT * DIMM];          // fp32 x kept for the gate epilogue
__device__ float g_er[TT * DIMM];
__device__ float g_ad[TT * DIMM];
__device__ float g_pA[KS * TT * DIMM];
__device__ float g_pB[KS * TT * DIMM];
__device__ float g_pS[KS * TT * SLOTSS];
__device__ float g_lg[TT * SLOTSS];
__device__ float g_c[TT * SLOTSS];
__device__ unsigned g_count = 0;
__device__ unsigned g_gen = 0;
__device__ unsigned g_cnt[2];

__device__ __forceinline__ float sigmoidf_(float v) { return 1.f / (1.f + expf(-v)); }

enum { M_RELU = 0, M_ID, M_LIG, M_GATE };

// -------- shared memory union --------
struct SmemG { __nv_bfloat16 As[2][64][SPAD]; __nv_bfloat16 Ws[2][64][SPAD]; };
struct SmemM { float cs[64][32]; float es[64][64]; float ds[64][64]; };
struct SmemS { float rowmax[64]; float psum[2][8]; };
union SmemU { SmemG g; SmemM m; SmemS s; };

// -------- software grid barrier --------
__device__ __forceinline__ void gridbar() {
    __threadfence();
    __syncthreads();
    if (threadIdx.x == 0) {
        unsigned gen = *(volatile unsigned*)&g_gen;
        unsigned prev = atomicAdd(&g_count, 1);
        if (prev == NB - 1) {
            g_count = 0;
            __threadfence();
            *(volatile unsigned*)&g_gen = gen + 1;
        } else {
            while (*(volatile unsigned*)&g_gen == gen) { __nanosleep(32); }
        }
        __threadfence();
    }
    __syncthreads();
}

__device__ __forceinline__ void spin_u32(volatile unsigned* p, unsigned target) {
    while (*p < target) { __nanosleep(64); }
}

// evict-first global load (single-use weights)
__device__ __forceinline__ float4 ldg_ef(const float* p) {
    float4 v;
    uint64_t pol;
    asm("createpolicy.fractional.L2::evict_first.b64 %0, 1.0;" : "=l"(pol));
    asm volatile("ld.global.nc.L2::cache_hint.v4.f32 {%0,%1,%2,%3}, [%4], %5;"
                 : "=f"(v.x), "=f"(v.y), "=f"(v.z), "=f"(v.w)
                 : "l"(p), "l"(pol));
    return v;
}

// fp32x4 -> packed bf16 hi (truncation) + lo (rn of exact remainder)
__device__ __forceinline__ void cvt_pair(float4 v, uint2& hi, uint2& lo) {
    uint32_t b0 = __float_as_uint(v.x), b1 = __float_as_uint(v.y);
    uint32_t b2 = __float_as_uint(v.z), b3 = __float_as_uint(v.w);
    hi.x = __byte_perm(b0, b1, 0x7632);
    hi.y = __byte_perm(b2, b3, 0x7632);
    float r0 = v.x - __uint_as_float(b0 & 0xFFFF0000u);
    float r1 = v.y - __uint_as_float(b1 & 0xFFFF0000u);
    float r2 = v.z - __uint_as_float(b2 & 0xFFFF0000u);
    float r3 = v.w - __uint_as_float(b3 & 0xFFFF0000u);
    __nv_bfloat162 l0 = __float22bfloat162_rn(make_float2(r0, r1));
    __nv_bfloat162 l1 = __float22bfloat162_rn(make_float2(r2, r3));
    lo.x = *(uint32_t*)&l0;
    lo.y = *(uint32_t*)&l1;
}

// -------- MMA helpers --------
__device__ __forceinline__ void ldsm4(uint32_t* r, uint32_t addr) {
    asm volatile("ldmatrix.sync.aligned.m8n8.x4.shared.b16 {%0,%1,%2,%3}, [%4];"
                 : "=r"(r[0]), "=r"(r[1]), "=r"(r[2]), "=r"(r[3]) : "r"(addr));
}
__device__ __forceinline__ void mma16816(float* d, const uint32_t* a, uint32_t b0, uint32_t b1) {
    asm volatile(
        "mma.sync.aligned.m16n8k16.row.col.f32.bf16.bf16.f32 "
        "{%0,%1,%2,%3}, {%4,%5,%6,%7}, {%8,%9}, {%0,%1,%2,%3};"
        : "+f"(d[0]), "+f"(d[1]), "+f"(d[2]), "+f"(d[3])
        : "r"(a[0]), "r"(a[1]), "r"(a[2]), "r"(a[3]), "r"(b0), "r"(b1));
}

// ---------------------------------------------------------------------------
// GEMM tile 64(M) x 64(N), K-slab 256.
// PREP=1: layer-1 A = traces gather + noise (fp32, converted in-loop).
// ABF=1 : A pre-converted bf16 hi/lo planes (no conversion, no math).
// ---------------------------------------------------------------------------
template <int PREP, int ABF>
__device__ void gemm_tile(SmemU* sm, const float* __restrict__ A,
                          const __nv_bfloat16* __restrict__ Abf,
                          const float* __restrict__ W, float* __restrict__ part,
                          int Ntot, int nblk, int tile,
                          const float* __restrict__ noise, const int* __restrict__ idx) {
    const int tid = threadIdx.x;
    const int nb = tile % nblk;
    const int kidx = tile / nblk;
    const int n0 = nb * 64;
    const int kb = kidx * KPER;

    const int a_row = tid >> 2, a_kq = (tid & 3) * 4;
    const float* Ag = nullptr;
    const float* Ng = nullptr;
    const __nv_bfloat16* Ahig = nullptr;
    const __nv_bfloat16* Alog = nullptr;
    if (ABF) {
        Ahig = Abf + (size_t)a_row * DIMM + kb + a_kq;
        Alog = Ahig + (size_t)TT * DIMM;
    } else if (PREP) {
        int row = __ldg(&idx[a_row]);
        Ag = A + (size_t)row * DIMM + kb + a_kq;
        Ng = noise + (size_t)a_row * DIMM + kb + a_kq;
    } else {
        Ag = A + (size_t)a_row * DIMM + kb + a_kq;
    }
    const int w_row = tid >> 2, w_kq = (tid & 3) * 4;
    const float* Wgp = W + (size_t)(n0 + w_row) * DIMM + kb + w_kq;

    const int lane = tid & 31, wid = tid >> 5;
    const int m0w = (wid & 1) * 32;
    const int n0w = (wid >> 1) * 16;
    const int gq = lane >> 3, rq = lane & 7;
    const int aoff = (m0w + (gq & 1) * 8 + rq) * SPAD + (gq >> 1) * 8;
    const int boff = (n0w + (gq >> 1) * 8 + rq) * SPAD + (gq & 1) * 8;

    const uint32_t asbase = (uint32_t)__cvta_generic_to_shared(&sm->g.As[0][0][0]);
    const uint32_t wsbase = (uint32_t)__cvta_generic_to_shared(&sm->g.Ws[0][0][0]);
    const uint32_t ABUF = 64 * SPAD * 2, WBUF = 64 * SPAD * 2;

    float4 av[3], wv[3];
    uint2 ah[3], al[3];

#define LOAD_CHUNK(st, c)                                                    \
    {                                                                        \
        if (ABF) {                                                           \
            ah[st] = __ldcg((const uint2*)(Ahig + (c) * 16));                \
            al[st] = __ldcg((const uint2*)(Alog + (c) * 16));                \
        } else {                                                             \
            float4 t4 = ldg_ef(Ag + (c) * 16);                               \
            if (PREP) {                                                      \
                float4 n4 = ldg_ef(Ng + (c) * 16);                           \
                t4.x = fmaf(0.01f, n4.x, t4.x);                              \
                t4.y = fmaf(0.01f, n4.y, t4.y);                              \
                t4.z = fmaf(0.01f, n4.z, t4.z);                              \
                t4.w = fmaf(0.01f, n4.w, t4.w);                              \
            }                                                                \
            av[st] = t4;                                                     \
        }                                                                    \
        wv[st] = ldg_ef(Wgp + (c) * 16);                                     \
    }
#define CVT_STORE(st, buf)                                                   \
    {                                                                        \
        if (ABF) {                                                           \
            *(uint2*)&sm->g.As[buf][a_row][a_kq] = ah[st];                   \
            *(uint2*)&sm->g.As[buf][a_row][a_kq + 16] = al[st];              \
        } else {                                                             \
            uint2 h2, l2;                                                    \
            cvt_pair(av[st], h2, l2);                                        \
            *(uint2*)&sm->g.As[buf][a_row][a_kq] = h2;                       \
            *(uint2*)&sm->g.As[buf][a_row][a_kq + 16] = l2;                  \
        }                                                                    \
        uint2 wh2, wl2;                                                      \
        cvt_pair(wv[st], wh2, wl2);                                          \
        *(uint2*)&sm->g.Ws[buf][w_row][w_kq] = wh2;                          \
        *(uint2*)&sm->g.Ws[buf][w_row][w_kq + 16] = wl2;                     \
    }

    LOAD_CHUNK(0, 0);
    LOAD_CHUNK(1, 1);
    LOAD_CHUNK(2, 2);
    CVT_STORE(0, 0);
    __syncthreads();

    float d[2][2][4];
#pragma unroll
    for (int mt = 0; mt < 2; mt++)
#pragma unroll
        for (int nf = 0; nf < 2; nf++)
#pragma unroll
            for (int j = 0; j < 4; j++) d[mt][nf][j] = 0.f;

#pragma unroll
    for (int c = 0; c < NCHUNK; c++) {
        const int cur = c & 1;
        if (c + 3 < NCHUNK) LOAD_CHUNK(c % 3, c + 3);

        uint32_t a[2][2][4], b[2][4];
#pragma unroll
        for (int mt = 0; mt < 2; mt++)
#pragma unroll
            for (int sec = 0; sec < 2; sec++)
                ldsm4(a[mt][sec], asbase + cur * ABUF + (uint32_t)(aoff + mt * 16 * SPAD + sec * 16) * 2);
#pragma unroll
        for (int sec = 0; sec < 2; sec++)
            ldsm4(b[sec], wsbase + cur * WBUF + (uint32_t)(boff + sec * 16) * 2);
#pragma unroll
        for (int q = 0; q < 3; q++) {
            const int as = (q == 2) ? 1 : 0;
            const int ws = (q == 1) ? 1 : 0;
#pragma unroll
            for (int mt = 0; mt < 2; mt++)
#pragma unroll
                for (int nf = 0; nf < 2; nf++)
                    mma16816(d[mt][nf], a[mt][as], b[ws][nf * 2], b[ws][nf * 2 + 1]);
        }
        if (c + 1 < NCHUNK) CVT_STORE((c + 1) % 3, cur ^ 1);
        __syncthreads();
    }
#undef LOAD_CHUNK
#undef CVT_STORE

    const int mbase = kidx * 64;
#pragma unroll
    for (int mt = 0; mt < 2; mt++)
#pragma unroll
        for (int nf = 0; nf < 2; nf++) {
            const int m = m0w + mt * 16 + (lane >> 2);
            const int n = n0 + n0w + nf * 8 + (lane & 3) * 2;
            *(float2*)&part[(size_t)(mbase + m) * Ntot + n] = make_float2(d[mt][nf][0], d[mt][nf][1]);
            *(float2*)&part[(size_t)(mbase + m + 8) * Ntot + n] = make_float2(d[mt][nf][2], d[mt][nf][3]);
        }
}

// ---------------------------------------------------------------------------
// reduce + activation; emits packed bf16 hi/lo planes (and optional fp32)
// ---------------------------------------------------------------------------
template <int MODE, int WF32>
__device__ void reduce_phase(const float* __restrict__ part, const float* __restrict__ bias,
                             __nv_bfloat16* __restrict__ outbf, float* __restrict__ outf,
                             const float* __restrict__ xbuf,
                             const float* __restrict__ vw, const float* __restrict__ vb) {
    if (threadIdx.x >= 128) return;
    const int f4 = blockIdx.x * 128 + threadIdx.x;  // 0..32767
    const int flat = f4 * 4;
    const int t = flat / DIMM;
    const int n = flat % DIMM;
    float acc[4] = {0.f, 0.f, 0.f, 0.f};
#pragma unroll
    for (int k = 0; k < KS; k++) {
        float4 p = __ldcg((const float4*)&part[(size_t)k * TT * DIMM + flat]);
        acc[0] += p.x; acc[1] += p.y; acc[2] += p.z; acc[3] += p.w;
    }
    float4 b4 = __ldg((const float4*)&bias[n]);
    float bb[4] = {b4.x, b4.y, b4.z, b4.w};
    float res[4];
    float4 xv;
    if (MODE == M_GATE) xv = __ldcg((const float4*)&xbuf[flat]);
    const float* xp = (const float*)&xv;
#pragma unroll
    for (int j = 0; j < 4; j++) {
        const float v = acc[j] + bb[j];
        if (MODE == M_RELU) {
            res[j] = v > 0.f ? v : 0.f;
        } else if (MODE == M_ID) {
            res[j] = v;
        } else if (MODE == M_LIG) {
            float ang = fmodf(0.37699111843077515f * (float)(t + 1), 6.2831853071795865f);
            float ps = -cosf(ang);
            float volt = sigmoidf_(fmaf(ps, __ldg(&vw[n + j]), __ldg(&vb[n + j])));
            res[j] = sigmoidf_(v) * volt;
        } else {  // M_GATE
            res[j] = xp[j] * sigmoidf_(v);
        }
    }
    uint2 h2, l2;
    cvt_pair(make_float4(res[0], res[1], res[2], res[3]), h2, l2);
    *(uint2*)&outbf[flat] = h2;
    *(uint2*)&outbf[TT * DIMM + flat] = l2;
    if (WF32)
        *(float4*)&outf[flat] = make_float4(res[0], res[1], res[2], res[3]);
}

// -------- tail reduce: er + ad (fp32 outputs for memupd) ---------------------
__device__ void tail_phase(const float* __restrict__ pA, const float* __restrict__ be,
                           const float* __restrict__ pB, const float* __restrict__ bad,
                           float* __restrict__ er, float* __restrict__ ad) {
    const int gid = blockIdx.x * 256 + threadIdx.x;
    if (gid >= 32768) return;
    const int flat = gid * 4;
    const int n = flat % DIMM;
    float aA[4] = {0, 0, 0, 0}, aB[4] = {0, 0, 0, 0};
#pragma unroll
    for (int k = 0; k < KS; k++) {
        float4 p = __ldcg((const float4*)&pA[(size_t)k * TT * DIMM + flat]);
        aA[0] += p.x; aA[1] += p.y; aA[2] += p.z; aA[3] += p.w;
        float4 q = __ldcg((const float4*)&pB[(size_t)k * TT * DIMM + flat]);
        aB[0] += q.x; aB[1] += q.y; aB[2] += q.z; aB[3] += q.w;
    }
    float4 e4 = __ldg((const float4*)&be[n]);
    float4 d4 = __ldg((const float4*)&bad[n]);
    const float* ep = (const float*)&e4;
    const float* dp = (const float*)&d4;
    float ro[4], ao[4];
#pragma unroll
    for (int j = 0; j < 4; j++) {
        ro[j] = sigmoidf_(aA[j] + ep[j]);
        ao[j] = aB[j] + dp[j];
    }
    *(float4*)&er[flat] = make_float4(ro[0], ro[1], ro[2], ro[3]);
    *(float4*)&ad[flat] = make_float4(ao[0], ao[1], ao[2], ao[3]);
}

// -------- softmax chain (block 0, 256 threads) ---------------------------------
__device__ void softmax_phase(SmemU* sm, const float* __restrict__ lg,
                              float* __restrict__ cbuf) {
    const int s = threadIdx.x, lane = s & 31, wid = s >> 5;
    __syncthreads();
#pragma unroll
    for (int r = 0; r < 8; r++) {
        const int row = wid * 8 + r;
        float m = -1e30f;
#pragma unroll
        for (int j = 0; j < 8; j++) m = fmaxf(m, __ldcg(&lg[row * SLOTSS + j * 32 + lane]));
#pragma unroll
        for (int o = 16; o > 0; o >>= 1) m = fmaxf(m, __shfl_xor_sync(0xffffffffu, m, o));
        if (lane == 0) sm->s.rowmax[row] = m;
    }
    __syncthreads();

    float usage = 0.f;
    for (int t = 0; t < TT; t++) {
        const float v = __ldcg(&lg[t * SLOTSS + s]) - 0.1f * usage - sm->s.rowmax[t];
        const float e = expf(v);
        float su = e;
#pragma unroll
        for (int o = 16; o > 0; o >>= 1) su += __shfl_xor_sync(0xffffffffu, su, o);
        if (lane == 0) sm->s.psum[t & 1][wid] = su;
        __syncthreads();
        float tot = 0.f;
#pragma unroll
        for (int i = 0; i < 8; i++) tot += sm->s.psum[t & 1][i];
        const float wgt = e / tot;
        cbuf[t * SLOTSS + s] = 0.5f * wgt;
        usage += wgt;
    }
}

// -------- memupd (tile 32 slots x 64 dims per block) ----------------------------
__device__ void memupd_phase(SmemU* sm, const float* __restrict__ cbuf,
                             const float* __restrict__ er, const float* __restrict__ ad,
                             const float* __restrict__ mem0, float* __restrict__ out) {
    const int tid = threadIdx.x;
    const int S0 = (blockIdx.x & 7) * 32;
    const int D0 = (blockIdx.x >> 3) * 64;
#pragma unroll
    for (int j = 0; j < 2; j++) {
        int f = tid + j * 256;
        int t = f >> 3, q = (f & 7) * 4;
        *(float4*)&sm->m.cs[t][q] = __ldcg((const float4*)&cbuf[(size_t)t * SLOTSS + S0 + q]);
    }
#pragma unroll
    for (int j = 0; j < 4; j++) {
        int f = tid + j * 256;
        int t = f >> 4, q = (f & 15) * 4;
        *(float4*)&sm->m.es[t][q] = __ldcg((const float4*)&er[(size_t)t * DIMM + D0 + q]);
        *(float4*)&sm->m.ds[t][q] = __ldcg((const float4*)&ad[(size_t)t * DIMM + D0 + q]);
    }
    __syncthreads();
    const int sg = (tid >> 4) * 2, dg = (tid & 15) * 4;
    float m[2][4];
#pragma unroll
    for (int j = 0; j < 2; j++)
        *(float4*)m[j] = __ldg((const float4*)&mem0[(size_t)(S0 + sg + j) * DIMM + D0 + dg]);
    for (int t = 0; t < 64; t++) {
        float c0 = sm->m.cs[t][sg], c1 = sm->m.cs[t][sg + 1];
        float4 e4 = *(const float4*)&sm->m.es[t][dg];
        float4 a4 = *(const float4*)&sm->m.ds[t][dg];
        float e[4] = {e4.x, e4.y, e4.z, e4.w};
        float a[4] = {a4.x, a4.y, a4.z, a4.w};
#pragma unroll
        for (int l = 0; l < 4; l++) {
            m[0][l] = fmaf(c0, fmaf(-e[l], m[0][l], a[l]), m[0][l]);
            m[1][l] = fmaf(c1, fmaf(-e[l], m[1][l], a[l]), m[1][l]);
        }
    }
#pragma unroll
    for (int j = 0; j < 2; j++)
        *(float4*)&out[(size_t)(S0 + sg + j) * DIMM + D0 + dg] = *(float4*)m[j];
}

// -------- mega kernel ------------------------------------------------------------
__global__ __launch_bounds__(256, 2) void mega_kernel(
    const float* __restrict__ traces, const float* __restrict__ noise,
    const float* __restrict__ mem0,
    const float* __restrict__ W1, const float* __restrict__ b1,
    const float* __restrict__ W2, const float* __restrict__ b2,
    const float* __restrict__ Wl, const float* __restrict__ bl,
    const float* __restrict__ vw, const float* __restrict__ vb,
    const float* __restrict__ Wg, const float* __restrict__ bg,
    const float* __restrict__ Wa, const float* __restrict__ ba,
    const float* __restrict__ We, const float* __restrict__ be,
    const float* __restrict__ Wad, const float* __restrict__ bad,
    const int* __restrict__ idx, float* __restrict__ out) {
    __shared__ SmemU sm;
    const int bid = blockIdx.x;
    const int tid = threadIdx.x;

    gemm_tile<1, 0>(&sm, traces, nullptr, W1, g_pA, DIMM, NBLK, bid, noise, idx);
    gridbar();
    reduce_phase<M_RELU, 0>(g_pA, b1, g_hbf, nullptr, nullptr, nullptr, nullptr);
    gridbar();

    gemm_tile<0, 1>(&sm, nullptr, g_hbf, W2, g_pA, DIMM, NBLK, bid, nullptr, nullptr);
    gridbar();
    reduce_phase<M_ID, 1>(g_pA, b2, g_xbf, g_x, nullptr, nullptr, nullptr);
    gridbar();

    gemm_tile<0, 1>(&sm, nullptr, g_xbf, Wl, g_pA, DIMM, NBLK, bid, nullptr, nullptr);
    gridbar();
    reduce_phase<M_LIG, 0>(g_pA, bl, g_lvbf, nullptr, nullptr, vw, vb);
    gridbar();

    gemm_tile<0, 1>(&sm, nullptr, g_lvbf, Wg, g_pA, DIMM, NBLK, bid, nullptr, nullptr);
    gridbar();
    reduce_phase<M_GATE, 0>(g_pA, bg, g_gatedbf, nullptr, g_x, nullptr, nullptr);
    gridbar();

    // ---- trio with overlapped softmax ----
    if (bid < 32) {
        gemm_tile<0, 1>(&sm, nullptr, g_gatedbf, Wa, g_pS, SLOTSS, 4, bid, nullptr, nullptr);
        __threadfence();
        __syncthreads();
        if (tid == 0) {
            atomicAdd(&g_cnt[0], 1u);
            spin_u32(&g_cnt[0], 32u);
        }
        __syncthreads();
        __threadfence();
        if (tid < 128) {
            const int flat = (bid * 128 + tid) * 4;
            const int ns = flat % SLOTSS;
            float aS[4] = {0, 0, 0, 0};
#pragma unroll
            for (int k = 0; k < KS; k++) {
                float4 p = __ldcg((const float4*)&g_pS[(size_t)k * TT * SLOTSS + flat]);
                aS[0] += p.x; aS[1] += p.y; aS[2] += p.z; aS[3] += p.w;
            }
            float4 b4 = __ldg((const float4*)&ba[ns]);
            *(float4*)&g_lg[flat] = make_float4(aS[0] + b4.x, aS[1] + b4.y, aS[2] + b4.z, aS[3] + b4.w);
        }
        __threadfence();
        __syncthreads();
        if (tid == 0) atomicAdd(&g_cnt[1], 1u);
    }

    if (bid == 0) {
        if (tid == 0) spin_u32(&g_cnt[1], 32u);
        __syncthreads();
        __threadfence();
        softmax_phase(&sm, g_lg, g_c);
    } else {
        const int tw = bid - 1;
        gemm_tile<0, 1>(&sm, nullptr, g_gatedbf, We, g_pA, DIMM, NBLK, tw, nullptr, nullptr);
        if (bid == 254) {
            __syncthreads();
            gemm_tile<0, 1>(&sm, nullptr, g_gatedbf, We, g_pA, DIMM, NBLK, 255, nullptr, nullptr);
        }
        __syncthreads();
        gemm_tile<0, 1>(&sm, nullptr, g_gatedbf, Wad, g_pB, DIMM, NBLK, tw, nullptr, nullptr);
        if (bid == 255) {
            __syncthreads();
            gemm_tile<0, 1>(&sm, nullptr, g_gatedbf, Wad, g_pB, DIMM, NBLK, 255, nullptr, nullptr);
        }
    }
    gridbar();

    tail_phase(g_pA, be, g_pB, bad, g_er, g_ad);
    gridbar();

    memupd_phase(&sm, g_c, g_er, g_ad, mem0, out);
}

// ---------------------------------------------------------------------------
extern "C" void kernel_launch(void* const* d_in, const int* in_sizes, int n_in,
                              void* d_out, int out_size) {
    const float* traces = (const float*)d_in[0];
    const float* noise  = (const float*)d_in[1];
    const float* mem0   = (const float*)d_in[2];
    const float* W1 = (const float*)d_in[4];
    const float* b1 = (const float*)d_in[5];
    const float* W2 = (const float*)d_in[6];
    const float* b2 = (const float*)d_in[7];
    const float* Wl = (const float*)d_in[8];
    const float* bl = (const float*)d_in[9];
    const float* vw = (const float*)d_in[10];
    const float* vb = (const float*)d_in[11];
    const float* Wg = (const float*)d_in[12];
    const float* bg = (const float*)d_in[13];
    const float* Wa = (const float*)d_in[14];
    const float* ba = (const float*)d_in[15];
    const float* We = (const float*)d_in[16];
    const float* be = (const float*)d_in[17];
    const float* Wad = (const float*)d_in[18];
    const float* bad = (const float*)d_in[19];
    const int* idx = (const int*)d_in[20];
    float* out = (float*)d_out;

    void* cnt_ptr = nullptr;
    cudaGetSymbolAddress(&cnt_ptr, g_cnt);
    cudaMemsetAsync(cnt_ptr, 0, sizeof(unsigned) * 2, 0);

    mega_kernel<<<NB, 256>>>(traces, noise, mem0, W1, b1, W2, b2, Wl, bl, vw, vb,
                             Wg, bg, Wa, ba, We, be, Wad, bad, idx, out);
}

// round 11
// speedup vs baseline: 1.0577x; 1.0577x over previous
#include <cuda_runtime.h>
#include <cuda_bf16.h>
#include <math.h>
#include <stdint.h>

#define TT 64
#define DIMM 2048
#define SLOTSS 256
#define KS 8
#define KPER (DIMM / KS)     // 256
#define NPAIR (KPER / 32)    // 8 iterations of 32-k
#define NBLK 32
#define SPAD2 72             // 32 hi + 32 lo + 8 pad (bf16 elems)
#define NB 256

// -------- device scratch --------
__device__ __nv_bfloat16 g_hbf[2 * TT * DIMM];
__device__ __nv_bfloat16 g_xbf[2 * TT * DIMM];
__device__ __nv_bfloat16 g_lvbf[2 * TT * DIMM];
__device__ __nv_bfloat16 g_gatedbf[2 * TT * DIMM];
__device__ float g_x[TT * DIMM];
__device__ float g_er[TT * DIMM];
__device__ float g_ad[TT * DIMM];
__device__ float g_pA[KS * TT * DIMM];
__device__ float g_pB[KS * TT * DIMM];
__device__ float g_pS[KS * TT * SLOTSS];
__device__ float g_lg[TT * SLOTSS];
__device__ float g_c[TT * SLOTSS];
__device__ unsigned g_count = 0;
__device__ unsigned g_gen = 0;
__device__ unsigned g_cnt[2];

__device__ __forceinline__ float sigmoidf_(float v) { return 1.f / (1.f + expf(-v)); }

enum { M_RELU = 0, M_ID, M_LIG, M_GATE };

// -------- shared memory union --------
struct SmemG { __nv_bfloat16 As[2][64][SPAD2]; __nv_bfloat16 Ws[2][64][SPAD2]; };  // 36864 B
struct SmemM { float cs[64][32]; float es[64][64]; float ds[64][64]; };            // 40960 B
struct SmemS { float rowmax[64]; float psum[2][8]; };
union __align__(16) SmemU { SmemG g; SmemM m; SmemS s; };

// -------- software grid barrier --------
__device__ __forceinline__ void gridbar() {
    __threadfence();
    __syncthreads();
    if (threadIdx.x == 0) {
        unsigned gen = *(volatile unsigned*)&g_gen;
        unsigned prev = atomicAdd(&g_count, 1);
        if (prev == NB - 1) {
            g_count = 0;
            __threadfence();
            *(volatile unsigned*)&g_gen = gen + 1;
        } else {
            while (*(volatile unsigned*)&g_gen == gen) { __nanosleep(32); }
        }
        __threadfence();
    }
    __syncthreads();
}

__device__ __forceinline__ void spin_u32(volatile unsigned* p, unsigned target) {
    while (*p < target) { __nanosleep(64); }
}

// evict-first global load (single-use weights)
__device__ __forceinline__ float4 ldg_ef(const float* p) {
    float4 v;
    uint64_t pol;
    asm("createpolicy.fractional.L2::evict_first.b64 %0, 1.0;" : "=l"(pol));
    asm volatile("ld.global.nc.L2::cache_hint.v4.f32 {%0,%1,%2,%3}, [%4], %5;"
                 : "=f"(v.x), "=f"(v.y), "=f"(v.z), "=f"(v.w)
                 : "l"(p), "l"(pol));
    return v;
}

// fp32x4 -> packed bf16 hi (truncation) + lo (rn of exact remainder)
__device__ __forceinline__ void cvt_pair(float4 v, uint2& hi, uint2& lo) {
    uint32_t b0 = __float_as_uint(v.x), b1 = __float_as_uint(v.y);
    uint32_t b2 = __float_as_uint(v.z), b3 = __float_as_uint(v.w);
    hi.x = __byte_perm(b0, b1, 0x7632);
    hi.y = __byte_perm(b2, b3, 0x7632);
    float r0 = v.x - __uint_as_float(b0 & 0xFFFF0000u);
    float r1 = v.y - __uint_as_float(b1 & 0xFFFF0000u);
    float r2 = v.z - __uint_as_float(b2 & 0xFFFF0000u);
    float r3 = v.w - __uint_as_float(b3 & 0xFFFF0000u);
    __nv_bfloat162 l0 = __float22bfloat162_rn(make_float2(r0, r1));
    __nv_bfloat162 l1 = __float22bfloat162_rn(make_float2(r2, r3));
    lo.x = *(uint32_t*)&l0;
    lo.y = *(uint32_t*)&l1;
}

// -------- MMA helpers --------
__device__ __forceinline__ void ldsm4(uint32_t* r, uint32_t addr) {
    asm volatile("ldmatrix.sync.aligned.m8n8.x4.shared.b16 {%0,%1,%2,%3}, [%4];"
                 : "=r"(r[0]), "=r"(r[1]), "=r"(r[2]), "=r"(r[3]) : "r"(addr));
}
__device__ __forceinline__ void mma16816(float* d, const uint32_t* a, uint32_t b0, uint32_t b1) {
    asm volatile(
        "mma.sync.aligned.m16n8k16.row.col.f32.bf16.bf16.f32 "
        "{%0,%1,%2,%3}, {%4,%5,%6,%7}, {%8,%9}, {%0,%1,%2,%3};"
        : "+f"(d[0]), "+f"(d[1]), "+f"(d[2]), "+f"(d[3])
        : "r"(a[0]), "r"(a[1]), "r"(a[2]), "r"(a[3]), "r"(b0), "r"(b1));
}

// ---------------------------------------------------------------------------
// GEMM tile 64(M) x 64(N), K-slab 256, 32-k per iteration (8 iters).
// Smem row layout: cols [0..32) = hi(k), [32..64) = lo(k), pad to 72.
// ---------------------------------------------------------------------------
template <int PREP, int ABF>
__device__ void gemm_tile(SmemU* sm, const float* __restrict__ A,
                          const __nv_bfloat16* __restrict__ Abf,
                          const float* __restrict__ W, float* __restrict__ part,
                          int Ntot, int nblk, int tile,
                          const float* __restrict__ noise, const int* __restrict__ idx) {
    const int tid = threadIdx.x;
    const int nb = tile % nblk;
    const int kidx = tile / nblk;
    const int n0 = nb * 64;
    const int kb = kidx * KPER;

    const int a_row = tid >> 2, a_k8 = (tid & 3) * 8;
    const float* Ag = nullptr;
    const float* Ng = nullptr;
    const __nv_bfloat16* Ahig = nullptr;
    const __nv_bfloat16* Alog = nullptr;
    if (ABF) {
        Ahig = Abf + (size_t)a_row * DIMM + kb + a_k8;
        Alog = Ahig + (size_t)TT * DIMM;
    } else {
        int row = PREP ? __ldg(&idx[a_row]) : a_row;
        Ag = A + (size_t)row * DIMM + kb + a_k8;
        if (PREP) Ng = noise + (size_t)a_row * DIMM + kb + a_k8;
    }
    const int w_row = tid >> 2, w_k8 = (tid & 3) * 8;
    const float* Wgp = W + (size_t)(n0 + w_row) * DIMM + kb + w_k8;

    const int lane = tid & 31, wid = tid >> 5;
    const int m0w = (wid & 1) * 32;
    const int n0w = (wid >> 1) * 16;
    const int gq = lane >> 3, rq = lane & 7;
    const int aoff = (m0w + (gq & 1) * 8 + rq) * SPAD2 + (gq >> 1) * 8;
    const int boff = (n0w + (gq >> 1) * 8 + rq) * SPAD2 + (gq & 1) * 8;

    const uint32_t asbase = (uint32_t)__cvta_generic_to_shared(&sm->g.As[0][0][0]);
    const uint32_t wsbase = (uint32_t)__cvta_generic_to_shared(&sm->g.Ws[0][0][0]);
    const uint32_t ABUF = 64 * SPAD2 * 2, WBUF = 64 * SPAD2 * 2;

    uint4 ahv[3], alv[3];
    float4 av0[3], av1[3];
    float4 wv0[3], wv1[3];

#define LOAD_PAIR(st, c)                                                     \
    {                                                                        \
        if (ABF) {                                                           \
            ahv[st] = __ldcg((const uint4*)(Ahig + (c) * 32));               \
            alv[st] = __ldcg((const uint4*)(Alog + (c) * 32));               \
        } else {                                                             \
            float4 t0 = __ldg((const float4*)(Ag + (c) * 32));               \
            float4 t1 = __ldg((const float4*)(Ag + (c) * 32 + 4));           \
            if (PREP) {                                                      \
                float4 m0 = __ldg((const float4*)(Ng + (c) * 32));           \
                float4 m1 = __ldg((const float4*)(Ng + (c) * 32 + 4));       \
                t0.x = fmaf(0.01f, m0.x, t0.x); t0.y = fmaf(0.01f, m0.y, t0.y); \
                t0.z = fmaf(0.01f, m0.z, t0.z); t0.w = fmaf(0.01f, m0.w, t0.w); \
                t1.x = fmaf(0.01f, m1.x, t1.x); t1.y = fmaf(0.01f, m1.y, t1.y); \
                t1.z = fmaf(0.01f, m1.z, t1.z); t1.w = fmaf(0.01f, m1.w, t1.w); \
            }                                                                \
            av0[st] = t0; av1[st] = t1;                                      \
        }                                                                    \
        wv0[st] = ldg_ef(Wgp + (c) * 32);                                    \
        wv1[st] = ldg_ef(Wgp + (c) * 32 + 4);                                \
    }
#define CVT_STORE(st, buf)                                                   \
    {                                                                        \
        if (ABF) {                                                           \
            *(uint4*)&sm->g.As[buf][a_row][a_k8] = ahv[st];                  \
            *(uint4*)&sm->g.As[buf][a_row][32 + a_k8] = alv[st];             \
        } else {                                                             \
            uint2 h0, l0, h1, l1;                                            \
            cvt_pair(av0[st], h0, l0);                                       \
            cvt_pair(av1[st], h1, l1);                                       \
            *(uint4*)&sm->g.As[buf][a_row][a_k8] = make_uint4(h0.x, h0.y, h1.x, h1.y); \
            *(uint4*)&sm->g.As[buf][a_row][32 + a_k8] = make_uint4(l0.x, l0.y, l1.x, l1.y); \
        }                                                                    \
        uint2 wh0, wl0, wh1, wl1;                                            \
        cvt_pair(wv0[st], wh0, wl0);                                         \
        cvt_pair(wv1[st], wh1, wl1);                                         \
        *(uint4*)&sm->g.Ws[buf][w_row][w_k8] = make_uint4(wh0.x, wh0.y, wh1.x, wh1.y); \
        *(uint4*)&sm->g.Ws[buf][w_row][32 + w_k8] = make_uint4(wl0.x, wl0.y, wl1.x, wl1.y); \
    }

    LOAD_PAIR(0, 0);
    LOAD_PAIR(1, 1);
    LOAD_PAIR(2, 2);
    CVT_STORE(0, 0);
    __syncthreads();

    float d[2][2][4];
#pragma unroll
    for (int mt = 0; mt < 2; mt++)
#pragma unroll
        for (int nf = 0; nf < 2; nf++)
#pragma unroll
            for (int j = 0; j < 4; j++) d[mt][nf][j] = 0.f;

#pragma unroll
    for (int ii = 0; ii < NPAIR; ii++) {
        const int cur = ii & 1;
        if (ii + 3 < NPAIR) LOAD_PAIR(ii % 3, ii + 3);

#pragma unroll
        for (int c16 = 0; c16 < 2; c16++) {
            uint32_t a[2][2][4], b[2][4];
#pragma unroll
            for (int mt = 0; mt < 2; mt++)
#pragma unroll
                for (int sec = 0; sec < 2; sec++)
                    ldsm4(a[mt][sec], asbase + cur * ABUF +
                          (uint32_t)(aoff + mt * 16 * SPAD2 + c16 * 16 + sec * 32) * 2);
#pragma unroll
            for (int sec = 0; sec < 2; sec++)
                ldsm4(b[sec], wsbase + cur * WBUF +
                      (uint32_t)(boff + c16 * 16 + sec * 32) * 2);
#pragma unroll
            for (int q = 0; q < 3; q++) {
                const int as = (q == 2) ? 1 : 0;
                const int ws = (q == 1) ? 1 : 0;
#pragma unroll
                for (int mt = 0; mt < 2; mt++)
#pragma unroll
                    for (int nf = 0; nf < 2; nf++)
                        mma16816(d[mt][nf], a[mt][as], b[ws][nf * 2], b[ws][nf * 2 + 1]);
            }
        }
        if (ii + 1 < NPAIR) CVT_STORE((ii + 1) % 3, cur ^ 1);
        __syncthreads();
    }
#undef LOAD_PAIR
#undef CVT_STORE

    const int mbase = kidx * 64;
#pragma unroll
    for (int mt = 0; mt < 2; mt++)
#pragma unroll
        for (int nf = 0; nf < 2; nf++) {
            const int m = m0w + mt * 16 + (lane >> 2);
            const int n = n0 + n0w + nf * 8 + (lane & 3) * 2;
            *(float2*)&part[(size_t)(mbase + m) * Ntot + n] = make_float2(d[mt][nf][0], d[mt][nf][1]);
            *(float2*)&part[(size_t)(mbase + m + 8) * Ntot + n] = make_float2(d[mt][nf][2], d[mt][nf][3]);
        }
}

// ---------------------------------------------------------------------------
// reduce + activation; emits packed bf16 hi/lo planes (and optional fp32)
// ---------------------------------------------------------------------------
template <int MODE, int WF32>
__device__ void reduce_phase(const float* __restrict__ part, const float* __restrict__ bias,
                             __nv_bfloat16* __restrict__ outbf, float* __restrict__ outf,
                             const float* __restrict__ xbuf,
                             const float* __restrict__ vw, const float* __restrict__ vb) {
    if (threadIdx.x >= 128) return;
    const int f4 = blockIdx.x * 128 + threadIdx.x;
    const int flat = f4 * 4;
    const int t = flat / DIMM;
    const int n = flat % DIMM;
    float acc[4] = {0.f, 0.f, 0.f, 0.f};
#pragma unroll
    for (int k = 0; k < KS; k++) {
        float4 p = __ldcg((const float4*)&part[(size_t)k * TT * DIMM + flat]);
        acc[0] += p.x; acc[1] += p.y; acc[2] += p.z; acc[3] += p.w;
    }
    float4 b4 = __ldg((const float4*)&bias[n]);
    float bb[4] = {b4.x, b4.y, b4.z, b4.w};
    float res[4];
    float4 xv;
    if (MODE == M_GATE) xv = __ldcg((const float4*)&xbuf[flat]);
    const float* xp = (const float*)&xv;
#pragma unroll
    for (int j = 0; j < 4; j++) {
        const float v = acc[j] + bb[j];
        if (MODE == M_RELU) {
            res[j] = v > 0.f ? v : 0.f;
        } else if (MODE == M_ID) {
            res[j] = v;
        } else if (MODE == M_LIG) {
            float ang = fmodf(0.37699111843077515f * (float)(t + 1), 6.2831853071795865f);
            float ps = -cosf(ang);
            float volt = sigmoidf_(fmaf(ps, __ldg(&vw[n + j]), __ldg(&vb[n + j])));
            res[j] = sigmoidf_(v) * volt;
        } else {  // M_GATE
            res[j] = xp[j] * sigmoidf_(v);
        }
    }
    uint2 h2, l2;
    cvt_pair(make_float4(res[0], res[1], res[2], res[3]), h2, l2);
    *(uint2*)&outbf[flat] = h2;
    *(uint2*)&outbf[TT * DIMM + flat] = l2;
    if (WF32)
        *(float4*)&outf[flat] = make_float4(res[0], res[1], res[2], res[3]);
}

// -------- tail reduce: er + ad ------------------------------------------------
__device__ void tail_phase(const float* __restrict__ pA, const float* __restrict__ be,
                           const float* __restrict__ pB, const float* __restrict__ bad,
                           float* __restrict__ er, float* __restrict__ ad) {
    const int gid = blockIdx.x * 256 + threadIdx.x;
    if (gid >= 32768) return;
    const int flat = gid * 4;
    const int n = flat % DIMM;
    float aA[4] = {0, 0, 0, 0}, aB[4] = {0, 0, 0, 0};
#pragma unroll
    for (int k = 0; k < KS; k++) {
        float4 p = __ldcg((const float4*)&pA[(size_t)k * TT * DIMM + flat]);
        aA[0] += p.x; aA[1] += p.y; aA[2] += p.z; aA[3] += p.w;
        float4 q = __ldcg((const float4*)&pB[(size_t)k * TT * DIMM + flat]);
        aB[0] += q.x; aB[1] += q.y; aB[2] += q.z; aB[3] += q.w;
    }
    float4 e4 = __ldg((const float4*)&be[n]);
    float4 d4 = __ldg((const float4*)&bad[n]);
    const float* ep = (const float*)&e4;
    const float* dp = (const float*)&d4;
    float ro[4], ao[4];
#pragma unroll
    for (int j = 0; j < 4; j++) {
        ro[j] = sigmoidf_(aA[j] + ep[j]);
        ao[j] = aB[j] + dp[j];
    }
    *(float4*)&er[flat] = make_float4(ro[0], ro[1], ro[2], ro[3]);
    *(float4*)&ad[flat] = make_float4(ao[0], ao[1], ao[2], ao[3]);
}

// -------- softmax chain (block 0) ---------------------------------------------
__device__ void softmax_phase(SmemU* sm, const float* __restrict__ lg,
                              float* __restrict__ cbuf) {
    const int s = threadIdx.x, lane = s & 31, wid = s >> 5;
    __syncthreads();
#pragma unroll
    for (int r = 0; r < 8; r++) {
        const int row = wid * 8 + r;
        float m = -1e30f;
#pragma unroll
        for (int j = 0; j < 8; j++) m = fmaxf(m, __ldcg(&lg[row * SLOTSS + j * 32 + lane]));
#pragma unroll
        for (int o = 16; o > 0; o >>= 1) m = fmaxf(m, __shfl_xor_sync(0xffffffffu, m, o));
        if (lane == 0) sm->s.rowmax[row] = m;
    }
    __syncthreads();

    float usage = 0.f;
    for (int t = 0; t < TT; t++) {
        const float v = __ldcg(&lg[t * SLOTSS + s]) - 0.1f * usage - sm->s.rowmax[t];
        const float e = expf(v);
        float su = e;
#pragma unroll
        for (int o = 16; o > 0; o >>= 1) su += __shfl_xor_sync(0xffffffffu, su, o);
        if (lane == 0) sm->s.psum[t & 1][wid] = su;
        __syncthreads();
        float tot = 0.f;
#pragma unroll
        for (int i = 0; i < 8; i++) tot += sm->s.psum[t & 1][i];
        const float wgt = e / tot;
        cbuf[t * SLOTSS + s] = 0.5f * wgt;
        usage += wgt;
    }
}

// -------- memupd (tile 32 slots x 64 dims per block) ----------------------------
__device__ void memupd_phase(SmemU* sm, const float* __restrict__ cbuf,
                             const float* __restrict__ er, const float* __restrict__ ad,
                             const float* __restrict__ mem0, float* __restrict__ out) {
    const int tid = threadIdx.x;
    const int S0 = (blockIdx.x & 7) * 32;
    const int D0 = (blockIdx.x >> 3) * 64;
#pragma unroll
    for (int j = 0; j < 2; j++) {
        int f = tid + j * 256;
        int t = f >> 3, q = (f & 7) * 4;
        *(float4*)&sm->m.cs[t][q] = __ldcg((const float4*)&cbuf[(size_t)t * SLOTSS + S0 + q]);
    }
#pragma unroll
    for (int j = 0; j < 4; j++) {
        int f = tid + j * 256;
        int t = f >> 4, q = (f & 15) * 4;
        *(float4*)&sm->m.es[t][q] = __ldcg((const float4*)&er[(size_t)t * DIMM + D0 + q]);
        *(float4*)&sm->m.ds[t][q] = __ldcg((const float4*)&ad[(size_t)t * DIMM + D0 + q]);
    }
    __syncthreads();
    const int sg = (tid >> 4) * 2, dg = (tid & 15) * 4;
    float m[2][4];
#pragma unroll
    for (int j = 0; j < 2; j++)
        *(float4*)m[j] = __ldg((const float4*)&mem0[(size_t)(S0 + sg + j) * DIMM + D0 + dg]);
    for (int t = 0; t < 64; t++) {
        float c0 = sm->m.cs[t][sg], c1 = sm->m.cs[t][sg + 1];
        float4 e4 = *(const float4*)&sm->m.es[t][dg];
        float4 a4 = *(const float4*)&sm->m.ds[t][dg];
        float e[4] = {e4.x, e4.y, e4.z, e4.w};
        float a[4] = {a4.x, a4.y, a4.z, a4.w};
#pragma unroll
        for (int l = 0; l < 4; l++) {
            m[0][l] = fmaf(c0, fmaf(-e[l], m[0][l], a[l]), m[0][l]);
            m[1][l] = fmaf(c1, fmaf(-e[l], m[1][l], a[l]), m[1][l]);
        }
    }
#pragma unroll
    for (int j = 0; j < 2; j++)
        *(float4*)&out[(size_t)(S0 + sg + j) * DIMM + D0 + dg] = *(float4*)m[j];
}

// -------- mega kernel ------------------------------------------------------------
__global__ __launch_bounds__(256, 2) void mega_kernel(
    const float* __restrict__ traces, const float* __restrict__ noise,
    const float* __restrict__ mem0,
    const float* __restrict__ W1, const float* __restrict__ b1,
    const float* __restrict__ W2, const float* __restrict__ b2,
    const float* __restrict__ Wl, const float* __restrict__ bl,
    const float* __restrict__ vw, const float* __restrict__ vb,
    const float* __restrict__ Wg, const float* __restrict__ bg,
    const float* __restrict__ Wa, const float* __restrict__ ba,
    const float* __restrict__ We, const float* __restrict__ be,
    const float* __restrict__ Wad, const float* __restrict__ bad,
    const int* __restrict__ idx, float* __restrict__ out) {
    __shared__ SmemU sm;
    const int bid = blockIdx.x;
    const int tid = threadIdx.x;

    gemm_tile<1, 0>(&sm, traces, nullptr, W1, g_pA, DIMM, NBLK, bid, noise, idx);
    gridbar();
    reduce_phase<M_RELU, 0>(g_pA, b1, g_hbf, nullptr, nullptr, nullptr, nullptr);
    gridbar();

    gemm_tile<0, 1>(&sm, nullptr, g_hbf, W2, g_pA, DIMM, NBLK, bid, nullptr, nullptr);
    gridbar();
    reduce_phase<M_ID, 1>(g_pA, b2, g_xbf, g_x, nullptr, nullptr, nullptr);
    gridbar();

    gemm_tile<0, 1>(&sm, nullptr, g_xbf, Wl, g_pA, DIMM, NBLK, bid, nullptr, nullptr);
    gridbar();
    reduce_phase<M_LIG, 0>(g_pA, bl, g_lvbf, nullptr, nullptr, vw, vb);
    gridbar();

    gemm_tile<0, 1>(&sm, nullptr, g_lvbf, Wg, g_pA, DIMM, NBLK, bid, nullptr, nullptr);
    gridbar();
    reduce_phase<M_GATE, 0>(g_pA, bg, g_gatedbf, nullptr, g_x, nullptr, nullptr);
    gridbar();

    // ---- trio with overlapped softmax ----
    if (bid < 32) {
        gemm_tile<0, 1>(&sm, nullptr, g_gatedbf, Wa, g_pS, SLOTSS, 4, bid, nullptr, nullptr);
        __threadfence();
        __syncthreads();
        if (tid == 0) {
            atomicAdd(&g_cnt[0], 1u);
            spin_u32(&g_cnt[0], 32u);
        }
        __syncthreads();
        __threadfence();
        if (tid < 128) {
            const int flat = (bid * 128 + tid) * 4;
            const int ns = flat % SLOTSS;
            float aS[4] = {0, 0, 0, 0};
#pragma unroll
            for (int k = 0; k < KS; k++) {
                float4 p = __ldcg((const float4*)&g_pS[(size_t)k * TT * SLOTSS + flat]);
                aS[0] += p.x; aS[1] += p.y; aS[2] += p.z; aS[3] += p.w;
            }
            float4 b4 = __ldg((const float4*)&ba[ns]);
            *(float4*)&g_lg[flat] = make_float4(aS[0] + b4.x, aS[1] + b4.y, aS[2] + b4.z, aS[3] + b4.w);
        }
        __threadfence();
        __syncthreads();
        if (tid == 0) atomicAdd(&g_cnt[1], 1u);
    }

    if (bid == 0) {
        if (tid == 0) spin_u32(&g_cnt[1], 32u);
        __syncthreads();
        __threadfence();
        softmax_phase(&sm, g_lg, g_c);
    } else {
        const int tw = bid - 1;
        gemm_tile<0, 1>(&sm, nullptr, g_gatedbf, We, g_pA, DIMM, NBLK, tw, nullptr, nullptr);
        if (bid == 254) {
            __syncthreads();
            gemm_tile<0, 1>(&sm, nullptr, g_gatedbf, We, g_pA, DIMM, NBLK, 255, nullptr, nullptr);
        }
        __syncthreads();
        gemm_tile<0, 1>(&sm, nullptr, g_gatedbf, Wad, g_pB, DIMM, NBLK, tw, nullptr, nullptr);
        if (bid == 255) {
            __syncthreads();
            gemm_tile<0, 1>(&sm, nullptr, g_gatedbf, Wad, g_pB, DIMM, NBLK, 255, nullptr, nullptr);
        }
    }
    gridbar();

    tail_phase(g_pA, be, g_pB, bad, g_er, g_ad);
    gridbar();

    memupd_phase(&sm, g_c, g_er, g_ad, mem0, out);
}

// ---------------------------------------------------------------------------
extern "C" void kernel_launch(void* const* d_in, const int* in_sizes, int n_in,
                              void* d_out, int out_size) {
    const float* traces = (const float*)d_in[0];
    const float* noise  = (const float*)d_in[1];
    const float* mem0   = (const float*)d_in[2];
    const float* W1 = (const float*)d_in[4];
    const float* b1 = (const float*)d_in[5];
    const float* W2 = (const float*)d_in[6];
    const float* b2 = (const float*)d_in[7];
    const float* Wl = (const float*)d_in[8];
    const float* bl = (const float*)d_in[9];
    const float* vw = (const float*)d_in[10];
    const float* vb = (const float*)d_in[11];
    const float* Wg = (const float*)d_in[12];
    const float* bg = (const float*)d_in[13];
    const float* Wa = (const float*)d_in[14];
    const float* ba = (const float*)d_in[15];
    const float* We = (const float*)d_in[16];
    const float* be = (const float*)d_in[17];
    const float* Wad = (const float*)d_in[18];
    const float* bad = (const float*)d_in[19];
    const int* idx = (const int*)d_in[20];
    float* out = (float*)d_out;

    void* cnt_ptr = nullptr;
    cudaGetSymbolAddress(&cnt_ptr, g_cnt);
    cudaMemsetAsync(cnt_ptr, 0, sizeof(unsigned) * 2, 0);

    mega_kernel<<<NB, 256>>>(traces, noise, mem0, W1, b1, W2, b2, Wl, bl, vw, vb,
                             Wg, bg, Wa, ba, We, be, Wad, bad, idx, out);
}